// round 1
// baseline (speedup 1.0000x reference)
#include <cuda_runtime.h>
#include <math.h>

// ---------------- problem constants ----------------
#define DIMK   1024
#define IMG_H  512
#define IMG_W  1408
#define CROPS  224
#define BB     2
#define NCC    6
#define NBB    32
#define NBOX   (BB*NBB)        // 64
#define NIMG   (NBOX*NCC)      // 384

// conv geometry
#define O1 56
#define O2 14
#define O3 7
#define N1 ((long long)NIMG*O1*O1)   // 1204224
#define N2 ((long long)NIMG*O2*O2)   // 75264
#define N3 ((long long)NIMG*O3*O3)   // 18816
#define K1 (3*7*7)     // 147
#define K2 (64*3*3)    // 576
#define K3 (256*3*3)   // 2304

// ---------------- scratch (device globals; no alloc) ----------------
__device__ float g_theta[NIMG*6];
__device__ int   g_valid[NIMG];
__device__ float g_crops[3LL*NIMG*CROPS*CROPS];     // [ch][img][y][x]
__device__ float g_X1[(long long)K1*N1];
__device__ float g_h1[64LL*N1];                     // [oc][img*pos]
__device__ float g_X2[(long long)K2*N2];
__device__ float g_h2[256LL*N2];
__device__ float g_X3[(long long)K3*N3];
__device__ float g_h3[1024LL*N3];
__device__ float g_tok[(long long)NIMG*50*DIMK];
__device__ float g_M[DIMK*DIMK];
__device__ float g_Wvo[DIMK*DIMK];
__device__ float g_S[NIMG*DIMK];
__device__ float g_CTX[NIMG*DIMK];
__device__ float g_EMB[NIMG*DIMK];

// ---------------- theta / projection ----------------
__global__ void theta_kernel(const float* __restrict__ boxes,
                             const float* __restrict__ la,
                             const float* __restrict__ l2i,
                             const float* __restrict__ aug,
                             const float* __restrict__ thw,
                             const float* __restrict__ thb)
{
    int t = blockIdx.x*blockDim.x + threadIdx.x;
    if (t >= NIMG) return;
    int c = t % NCC; int n = t / NCC; int b = n / NBB; int nb = n % NBB;
    const float* bx = boxes + (b*NBB + nb)*9;

    float r[4];
    #pragma unroll
    for (int i = 0; i < 4; i++) {
        float s = thb[i];
        #pragma unroll
        for (int j = 0; j < 9; j++) s += bx[j]*thw[i*9+j];
        r[i] = tanhf(s);
    }

    const float* L = la + b*16;
    float cx = bx[0]-L[3], cy = bx[1]-L[7], cz = bx[2]-L[11];
    float a00=L[0],a01=L[1],a02=L[2],a10=L[4],a11=L[5],a12=L[6],a20=L[8],a21=L[9],a22=L[10];
    float det = a00*(a11*a22-a12*a21) - a01*(a10*a22-a12*a20) + a02*(a10*a21-a11*a20);
    float id = 1.f/det;
    float x = ((a11*a22-a12*a21)*cx + (a02*a21-a01*a22)*cy + (a01*a12-a02*a11)*cz)*id;
    float y = ((a12*a20-a10*a22)*cx + (a00*a22-a02*a20)*cy + (a02*a10-a00*a12)*cz)*id;
    float z = ((a10*a21-a11*a20)*cx + (a01*a20-a00*a21)*cy + (a00*a11-a01*a10)*cz)*id;

    const float* P = l2i + (b*NCC + c)*16;
    float px = P[0]*x + P[1]*y + P[2]*z  + P[3];
    float py = P[4]*x + P[5]*y + P[6]*z  + P[7];
    float pz = P[8]*x + P[9]*y + P[10]*z + P[11];
    float zz = fminf(fmaxf(pz, 1e-5f), 100000.f);
    float qx = px/zz, qy = py/zz;
    const float* A = aug + (b*NCC + c)*16;
    float ux = A[0]*qx + A[1]*qy + A[2]*zz + A[3];
    float uy = A[4]*qx + A[5]*qy + A[6]*zz + A[7];

    int on = (uy < (float)IMG_H) && (uy >= 0.f) && (ux < (float)IMG_W) && (ux >= 0.f);
    float ty = uy/(float)IMG_H*2.f - 1.f;
    float tx = ux/(float)IMG_W*2.f - 1.f;

    g_theta[t*6+0]=r[0]; g_theta[t*6+1]=r[1]; g_theta[t*6+2]=tx;
    g_theta[t*6+3]=r[2]; g_theta[t*6+4]=r[3]; g_theta[t*6+5]=ty;
    g_valid[t] = on;
}

// ---------------- grid sample -> crops ----------------
__global__ void sample_kernel(const float* __restrict__ imgs)
{
    long long idx = (long long)blockIdx.x*blockDim.x + threadIdx.x;
    long long total = (long long)NIMG*CROPS*CROPS;
    if (idx >= total) return;
    int x = (int)(idx % CROPS);
    int y = (int)((idx / CROPS) % CROPS);
    int ii = (int)(idx / (CROPS*CROPS));
    int c = ii % NCC; int n = ii / NCC; int b = n / NBB;

    float t0 = g_theta[ii*6+0], t1 = g_theta[ii*6+1], t2 = g_theta[ii*6+2];
    float t3 = g_theta[ii*6+3], t4 = g_theta[ii*6+4], t5 = g_theta[ii*6+5];

    float gx = (2.f*x + 1.f)/(float)CROPS - 1.f;
    float gy = (2.f*y + 1.f)/(float)CROPS - 1.f;
    float g0 = gx*t0 + gy*t1 + t2;
    float g1 = gx*t3 + gy*t4 + t5;
    float ixf = ((g0 + 1.f)*(float)IMG_W - 1.f)*0.5f;
    float iyf = ((g1 + 1.f)*(float)IMG_H - 1.f)*0.5f;
    float x0 = floorf(ixf), y0 = floorf(iyf);
    float wx = ixf - x0,    wy = iyf - y0;
    float x1 = x0 + 1.f,    y1 = y0 + 1.f;
    bool vx0 = (x0 >= 0.f) && (x0 <= (float)(IMG_W-1));
    bool vx1 = (x1 >= 0.f) && (x1 <= (float)(IMG_W-1));
    bool vy0 = (y0 >= 0.f) && (y0 <= (float)(IMG_H-1));
    bool vy1 = (y1 >= 0.f) && (y1 <= (float)(IMG_H-1));
    int xi0 = (int)fminf(fmaxf(x0,0.f),(float)(IMG_W-1));
    int xi1 = (int)fminf(fmaxf(x1,0.f),(float)(IMG_W-1));
    int yi0 = (int)fminf(fmaxf(y0,0.f),(float)(IMG_H-1));
    int yi1 = (int)fminf(fmaxf(y1,0.f),(float)(IMG_H-1));
    float w00=(1.f-wx)*(1.f-wy), w01=wx*(1.f-wy), w10=(1.f-wx)*wy, w11=wx*wy;

    const float* base = imgs + (long long)(b*NCC + c)*3LL*IMG_H*IMG_W;
    #pragma unroll
    for (int ch = 0; ch < 3; ch++) {
        const float* im = base + (long long)ch*IMG_H*IMG_W;
        float v00 = (vx0&&vy0) ? im[yi0*IMG_W + xi0] : 0.f;
        float v01 = (vx1&&vy0) ? im[yi0*IMG_W + xi1] : 0.f;
        float v10 = (vx0&&vy1) ? im[yi1*IMG_W + xi0] : 0.f;
        float v11 = (vx1&&vy1) ? im[yi1*IMG_W + xi1] : 0.f;
        g_crops[((long long)(ch*NIMG + ii)*CROPS + y)*CROPS + x] =
            v00*w00 + v01*w01 + v10*w10 + v11*w11;
    }
}

// ---------------- im2col kernels ----------------
__global__ void im2col1_kernel()
{
    long long e = (long long)blockIdx.x*blockDim.x + threadIdx.x;
    long long total = (long long)K1*N1;
    if (e >= total) return;
    int n1 = (int)(e % N1); int k = (int)(e / N1);
    int kx = k % 7, ky = (k/7) % 7, ch = k/49;
    int pos = n1 % (O1*O1); int img = n1 / (O1*O1);
    int ox = pos % O1, oy = pos / O1;
    int iy = oy*4 - 1 + ky, ix = ox*4 - 1 + kx;
    float v = 0.f;
    if (iy >= 0 && iy < CROPS && ix >= 0 && ix < CROPS)
        v = g_crops[((long long)(ch*NIMG + img)*CROPS + iy)*CROPS + ix];
    g_X1[e] = v;
}
__global__ void im2col2_kernel()
{
    long long e = (long long)blockIdx.x*blockDim.x + threadIdx.x;
    long long total = (long long)K2*N2;
    if (e >= total) return;
    int n2 = (int)(e % N2); int k = (int)(e / N2);
    int kx = k % 3, ky = (k/3) % 3, ic = k/9;
    int pos = n2 % (O2*O2); int img = n2 / (O2*O2);
    int ox = pos % O2, oy = pos / O2;
    int iy = oy*4 + ky, ix = ox*4 + kx;   // no padding, always in range
    g_X2[e] = g_h1[(long long)ic*N1 + (long long)img*(O1*O1) + iy*O1 + ix];
}
__global__ void im2col3_kernel()
{
    long long e = (long long)blockIdx.x*blockDim.x + threadIdx.x;
    long long total = (long long)K3*N3;
    if (e >= total) return;
    int n3 = (int)(e % N3); int k = (int)(e / N3);
    int kx = k % 3, ky = (k/3) % 3, ic = k/9;
    int pos = n3 % (O3*O3); int img = n3 / (O3*O3);
    int ox = pos % O3, oy = pos / O3;
    int iy = oy*2 + ky, ix = ox*2 + kx;   // pad hi=1
    float v = 0.f;
    if (iy < O2 && ix < O2)
        v = g_h2[(long long)ic*N2 + (long long)img*(O2*O2) + iy*O2 + ix];
    g_X3[e] = v;
}

// ---------------- SGEMM: C[M][N] = A[M][K] * B(K,N), optional B^T, optional relu --------
#define BM 128
#define BN 128
#define BK 8
#define TM 8
#define TN 8

__global__ __launch_bounds__(256) void sgemm_kernel(
    const float* __restrict__ A, const float* __restrict__ B, float* __restrict__ C,
    int M, int N, int K, int lda, int ldb, int ldc, int transb, int relu)
{
    __shared__ float As[BK][BM+4];
    __shared__ float Bs[BK][BN];
    int tid = threadIdx.x;
    int tcol = tid & 15;     // N dir
    int trow = tid >> 4;     // M dir
    int bx = blockIdx.x, by = blockIdx.y;
    int rowC = by*BM + trow*TM;
    int colC = bx*BN + tcol*TN;

    float acc[TM][TN];
    #pragma unroll
    for (int i=0;i<TM;i++)
        #pragma unroll
        for (int j=0;j<TN;j++) acc[i][j] = 0.f;

    for (int k0 = 0; k0 < K; k0 += BK) {
        #pragma unroll
        for (int i = 0; i < 4; i++) {
            int idx = tid + i*256;
            int ar = idx >> 3, ac = idx & 7;
            int gr = by*BM + ar, gc = k0 + ac;
            As[ac][ar] = (gr < M && gc < K) ? A[(long long)gr*lda + gc] : 0.f;
            int br = idx >> 7, bc = idx & 127;
            int gk = k0 + br, gn = bx*BN + bc;
            float bv = 0.f;
            if (gk < K && gn < N)
                bv = transb ? B[(long long)gn*ldb + gk] : B[(long long)gk*ldb + gn];
            Bs[br][bc] = bv;
        }
        __syncthreads();
        #pragma unroll
        for (int kk = 0; kk < BK; kk++) {
            float ra[TM], rb[TN];
            const float4* a4 = reinterpret_cast<const float4*>(&As[kk][trow*TM]);
            float4 av0 = a4[0], av1 = a4[1];
            ra[0]=av0.x; ra[1]=av0.y; ra[2]=av0.z; ra[3]=av0.w;
            ra[4]=av1.x; ra[5]=av1.y; ra[6]=av1.z; ra[7]=av1.w;
            const float4* b4 = reinterpret_cast<const float4*>(&Bs[kk][tcol*TN]);
            float4 bv0 = b4[0], bv1 = b4[1];
            rb[0]=bv0.x; rb[1]=bv0.y; rb[2]=bv0.z; rb[3]=bv0.w;
            rb[4]=bv1.x; rb[5]=bv1.y; rb[6]=bv1.z; rb[7]=bv1.w;
            #pragma unroll
            for (int i=0;i<TM;i++)
                #pragma unroll
                for (int j=0;j<TN;j++)
                    acc[i][j] += ra[i]*rb[j];
        }
        __syncthreads();
    }
    #pragma unroll
    for (int i=0;i<TM;i++) {
        int r = rowC + i; if (r >= M) continue;
        #pragma unroll
        for (int j=0;j<TN;j++) {
            int cc = colC + j; if (cc >= N) continue;
            float v = acc[i][j];
            if (relu) v = fmaxf(v, 0.f);
            C[(long long)r*ldc + cc] = v;
        }
    }
}

// ---------------- tokens ----------------
__global__ void tok_kernel(const float* __restrict__ pos_embed)
{
    int i = blockIdx.x;
    for (int d = threadIdx.x; d < DIMK; d += blockDim.x) {
        const float* hp = g_h3 + (long long)d*N3 + (long long)i*49;
        float s = 0.f;
        #pragma unroll 7
        for (int p = 0; p < 49; p++) {
            float v = hp[p];
            s += v;
            g_tok[((long long)i*50 + 1 + p)*DIMK + d] = v + pos_embed[(1+p)*DIMK + d];
        }
        g_tok[(long long)i*50*DIMK + d] = s*(1.f/49.f) + pos_embed[d];
    }
}

// ---------------- attention (per image): logits/softmax/context -------------
__global__ void attn_kernel()
{
    int i = blockIdx.x;
    __shared__ float sS[DIMK];
    __shared__ float slog[64];
    const float* t = g_tok + (long long)i*50*DIMK;
    for (int d = threadIdx.x; d < DIMK; d += blockDim.x) sS[d] = g_S[i*DIMK + d];
    __syncthreads();

    int w = threadIdx.x >> 5, lane = threadIdx.x & 31;
    for (int j = w; j < 50; j += 8) {
        const float* tj = t + (long long)j*DIMK;
        float s = 0.f;
        for (int d = lane; d < DIMK; d += 32) s += sS[d]*tj[d];
        #pragma unroll
        for (int o = 16; o > 0; o >>= 1) s += __shfl_down_sync(0xffffffff, s, o);
        if (lane == 0) slog[j] = s * 0.03125f;   // DIM^-0.5
    }
    __syncthreads();
    if (threadIdx.x == 0) {
        float mx = slog[0];
        for (int j = 1; j < 50; j++) mx = fmaxf(mx, slog[j]);
        float sum = 0.f;
        for (int j = 0; j < 50; j++) { float e = expf(slog[j]-mx); slog[j]=e; sum+=e; }
        float inv = 1.f/sum;
        for (int j = 0; j < 50; j++) slog[j] *= inv;
    }
    __syncthreads();
    for (int d = threadIdx.x; d < DIMK; d += blockDim.x) {
        float c = 0.f;
        #pragma unroll 10
        for (int j = 0; j < 50; j++) c += slog[j]*t[(long long)j*DIMK + d];
        g_CTX[i*DIMK + d] = c;
    }
}

// ---------------- final EMA fuse ----------------
__global__ void fuse_kernel(const float* __restrict__ bdd,
                            const float* __restrict__ momentum,
                            float* __restrict__ out)
{
    int n = blockIdx.x;
    float mom = *momentum;
    const int order[6] = {2,0,1,5,3,4};
    for (int d = threadIdx.x; d < DIMK; d += blockDim.x) {
        float e = bdd[d];
        #pragma unroll
        for (int k = 0; k < 6; k++) {
            int c = order[k];
            int ii = n*NCC + c;
            if (g_valid[ii]) e = mom*e + (1.f - mom)*g_EMB[(long long)ii*DIMK + d];
        }
        out[n*DIMK + d] = e;
    }
}

// ---------------- launch ----------------
static inline float* sym(const void* s) {
    void* p = nullptr;
    cudaGetSymbolAddress(&p, s);
    return (float*)p;
}

extern "C" void kernel_launch(void* const* d_in, const int* in_sizes, int n_in,
                              void* d_out, int out_size)
{
    const float* camera_imgs = (const float*)d_in[0];
    const float* pred_boxes  = (const float*)d_in[1];
    const float* img_aug     = (const float*)d_in[2];
    const float* lidar_aug   = (const float*)d_in[3];
    const float* lidar2img   = (const float*)d_in[4];
    const float* momentum    = (const float*)d_in[5];
    const float* bdd         = (const float*)d_in[6];
    const float* theta_w     = (const float*)d_in[7];
    const float* theta_b     = (const float*)d_in[8];
    const float* conv1       = (const float*)d_in[9];
    const float* conv2       = (const float*)d_in[10];
    const float* conv3       = (const float*)d_in[11];
    const float* pos_embed   = (const float*)d_in[12];
    const float* wq          = (const float*)d_in[13];
    const float* wk          = (const float*)d_in[14];
    const float* wv          = (const float*)d_in[15];
    const float* wo          = (const float*)d_in[16];
    float* out = (float*)d_out;

    float* pX1  = sym(g_X1);   float* ph1 = sym(g_h1);
    float* pX2  = sym(g_X2);   float* ph2 = sym(g_h2);
    float* pX3  = sym(g_X3);   float* ph3 = sym(g_h3);
    float* ptok = sym(g_tok);  float* pM  = sym(g_M);
    float* pWvo = sym(g_Wvo);  float* pS  = sym(g_S);
    float* pCTX = sym(g_CTX);  float* pEMB= sym(g_EMB);

    // precompute M = wq @ wk^T ; Wvo = wv @ wo  (overlaps with early pipeline on same stream)
    {
        dim3 g(DIMK/BN, DIMK/BM);
        sgemm_kernel<<<g,256>>>(wq, wk, pM,  DIMK, DIMK, DIMK, DIMK, DIMK, DIMK, 1, 0);
        sgemm_kernel<<<g,256>>>(wv, wo, pWvo,DIMK, DIMK, DIMK, DIMK, DIMK, DIMK, 0, 0);
    }

    // projection / theta
    theta_kernel<<<2,192>>>(pred_boxes, lidar_aug, lidar2img, img_aug, theta_w, theta_b);

    // grid sample
    {
        long long total = (long long)NIMG*CROPS*CROPS;
        sample_kernel<<<(unsigned)((total+255)/256),256>>>(camera_imgs);
    }

    // conv1
    {
        long long total = (long long)K1*N1;
        im2col1_kernel<<<(unsigned)((total+255)/256),256>>>();
        dim3 g((unsigned)((N1+BN-1)/BN), 1);
        sgemm_kernel<<<g,256>>>(conv1, pX1, ph1, 64, (int)N1, K1, K1, (int)N1, (int)N1, 0, 1);
    }
    // conv2
    {
        long long total = (long long)K2*N2;
        im2col2_kernel<<<(unsigned)((total+255)/256),256>>>();
        dim3 g((unsigned)((N2+BN-1)/BN), 2);
        sgemm_kernel<<<g,256>>>(conv2, pX2, ph2, 256, (int)N2, K2, K2, (int)N2, (int)N2, 0, 1);
    }
    // conv3
    {
        long long total = (long long)K3*N3;
        im2col3_kernel<<<(unsigned)((total+255)/256),256>>>();
        dim3 g((unsigned)((N3+BN-1)/BN), 8);
        sgemm_kernel<<<g,256>>>(conv3, pX3, ph3, 1024, (int)N3, K3, K3, (int)N3, (int)N3, 0, 1);
    }

    // tokens (+ pos embed, cls mean)
    tok_kernel<<<NIMG,256>>>(pos_embed);

    // S = tok0 @ M   (A rows strided by 50*DIMK)
    {
        dim3 g(DIMK/BN, (NIMG+BM-1)/BM);
        sgemm_kernel<<<g,256>>>(ptok, pM, pS, NIMG, DIMK, DIMK, 50*DIMK, DIMK, DIMK, 0, 0);
    }

    // softmax + context
    attn_kernel<<<NIMG,256>>>();

    // EMB = CTX @ Wvo
    {
        dim3 g(DIMK/BN, (NIMG+BM-1)/BM);
        sgemm_kernel<<<g,256>>>(pCTX, pWvo, pEMB, NIMG, DIMK, DIMK, DIMK, DIMK, DIMK, 0, 0);
    }

    // EMA fuse -> out (64 x 1024)
    fuse_kernel<<<NBOX,256>>>(bdd, momentum, out);
}

// round 2
// speedup vs baseline: 2.8812x; 2.8812x over previous
#include <cuda_runtime.h>
#include <math.h>

// ---------------- problem constants ----------------
#define DIMK   1024
#define IMG_H  512
#define IMG_W  1408
#define CROPS  224
#define BB     2
#define NCC    6
#define NBB    32
#define NBOX   (BB*NBB)        // 64
#define NIMG   (NBOX*NCC)      // 384

// conv geometry
#define O1 56
#define O2 14
#define O3 7
#define N1 ((long long)NIMG*O1*O1)   // 1204224
#define N2 ((long long)NIMG*O2*O2)   // 75264
#define N3 ((long long)NIMG*O3*O3)   // 18816
#define K1 (3*7*7)     // 147
#define K2 (64*3*3)    // 576
#define K3 (256*3*3)   // 2304

// ---------------- scratch (device globals; no alloc) ----------------
__device__ float g_theta[NIMG*6];
__device__ int   g_valid[NIMG];
__device__ float g_crops[3LL*NIMG*CROPS*CROPS];     // [ch][img][y][x]
__device__ float g_X1[(long long)K1*N1];
__device__ float g_h1[64LL*N1];                     // [oc][img*pos]
__device__ float g_X2[(long long)K2*N2];
__device__ float g_h2[256LL*N2];
__device__ float g_X3[(long long)K3*N3];
__device__ float g_h3[1024LL*N3];
__device__ float g_tok[(long long)NIMG*50*DIMK];
__device__ float g_M[DIMK*DIMK];
__device__ float g_Wvo[DIMK*DIMK];
__device__ float g_S[NIMG*DIMK];
__device__ float g_CTX[NIMG*DIMK];
__device__ float g_EMB[NIMG*DIMK];

// ---------------- theta / projection ----------------
__global__ void theta_kernel(const float* __restrict__ boxes,
                             const float* __restrict__ la,
                             const float* __restrict__ l2i,
                             const float* __restrict__ aug,
                             const float* __restrict__ thw,
                             const float* __restrict__ thb)
{
    int t = blockIdx.x*blockDim.x + threadIdx.x;
    if (t >= NIMG) return;
    int c = t % NCC; int n = t / NCC; int b = n / NBB; int nb = n % NBB;
    const float* bx = boxes + (b*NBB + nb)*9;

    float r[4];
    #pragma unroll
    for (int i = 0; i < 4; i++) {
        float s = thb[i];
        #pragma unroll
        for (int j = 0; j < 9; j++) s += bx[j]*thw[i*9+j];
        r[i] = tanhf(s);
    }

    const float* L = la + b*16;
    float cx = bx[0]-L[3], cy = bx[1]-L[7], cz = bx[2]-L[11];
    float a00=L[0],a01=L[1],a02=L[2],a10=L[4],a11=L[5],a12=L[6],a20=L[8],a21=L[9],a22=L[10];
    float det = a00*(a11*a22-a12*a21) - a01*(a10*a22-a12*a20) + a02*(a10*a21-a11*a20);
    float id = 1.f/det;
    float x = ((a11*a22-a12*a21)*cx + (a02*a21-a01*a22)*cy + (a01*a12-a02*a11)*cz)*id;
    float y = ((a12*a20-a10*a22)*cx + (a00*a22-a02*a20)*cy + (a02*a10-a00*a12)*cz)*id;
    float z = ((a10*a21-a11*a20)*cx + (a01*a20-a00*a21)*cy + (a00*a11-a01*a10)*cz)*id;

    const float* P = l2i + (b*NCC + c)*16;
    float px = P[0]*x + P[1]*y + P[2]*z  + P[3];
    float py = P[4]*x + P[5]*y + P[6]*z  + P[7];
    float pz = P[8]*x + P[9]*y + P[10]*z + P[11];
    float zz = fminf(fmaxf(pz, 1e-5f), 100000.f);
    float qx = px/zz, qy = py/zz;
    const float* A = aug + (b*NCC + c)*16;
    float ux = A[0]*qx + A[1]*qy + A[2]*zz + A[3];
    float uy = A[4]*qx + A[5]*qy + A[6]*zz + A[7];

    int on = (uy < (float)IMG_H) && (uy >= 0.f) && (ux < (float)IMG_W) && (ux >= 0.f);
    float ty = uy/(float)IMG_H*2.f - 1.f;
    float tx = ux/(float)IMG_W*2.f - 1.f;

    g_theta[t*6+0]=r[0]; g_theta[t*6+1]=r[1]; g_theta[t*6+2]=tx;
    g_theta[t*6+3]=r[2]; g_theta[t*6+4]=r[3]; g_theta[t*6+5]=ty;
    g_valid[t] = on;
}

// ---------------- grid sample -> crops ----------------
__global__ void sample_kernel(const float* __restrict__ imgs)
{
    long long idx = (long long)blockIdx.x*blockDim.x + threadIdx.x;
    long long total = (long long)NIMG*CROPS*CROPS;
    if (idx >= total) return;
    int x = (int)(idx % CROPS);
    int y = (int)((idx / CROPS) % CROPS);
    int ii = (int)(idx / (CROPS*CROPS));
    int c = ii % NCC; int n = ii / NCC; int b = n / NBB;

    float t0 = g_theta[ii*6+0], t1 = g_theta[ii*6+1], t2 = g_theta[ii*6+2];
    float t3 = g_theta[ii*6+3], t4 = g_theta[ii*6+4], t5 = g_theta[ii*6+5];

    float gx = (2.f*x + 1.f)/(float)CROPS - 1.f;
    float gy = (2.f*y + 1.f)/(float)CROPS - 1.f;
    float g0 = gx*t0 + gy*t1 + t2;
    float g1 = gx*t3 + gy*t4 + t5;
    float ixf = ((g0 + 1.f)*(float)IMG_W - 1.f)*0.5f;
    float iyf = ((g1 + 1.f)*(float)IMG_H - 1.f)*0.5f;
    float x0 = floorf(ixf), y0 = floorf(iyf);
    float wx = ixf - x0,    wy = iyf - y0;
    float x1 = x0 + 1.f,    y1 = y0 + 1.f;
    bool vx0 = (x0 >= 0.f) && (x0 <= (float)(IMG_W-1));
    bool vx1 = (x1 >= 0.f) && (x1 <= (float)(IMG_W-1));
    bool vy0 = (y0 >= 0.f) && (y0 <= (float)(IMG_H-1));
    bool vy1 = (y1 >= 0.f) && (y1 <= (float)(IMG_H-1));
    int xi0 = (int)fminf(fmaxf(x0,0.f),(float)(IMG_W-1));
    int xi1 = (int)fminf(fmaxf(x1,0.f),(float)(IMG_W-1));
    int yi0 = (int)fminf(fmaxf(y0,0.f),(float)(IMG_H-1));
    int yi1 = (int)fminf(fmaxf(y1,0.f),(float)(IMG_H-1));
    float w00=(1.f-wx)*(1.f-wy), w01=wx*(1.f-wy), w10=(1.f-wx)*wy, w11=wx*wy;

    const float* base = imgs + (long long)(b*NCC + c)*3LL*IMG_H*IMG_W;
    #pragma unroll
    for (int ch = 0; ch < 3; ch++) {
        const float* im = base + (long long)ch*IMG_H*IMG_W;
        float v00 = (vx0&&vy0) ? im[yi0*IMG_W + xi0] : 0.f;
        float v01 = (vx1&&vy0) ? im[yi0*IMG_W + xi1] : 0.f;
        float v10 = (vx0&&vy1) ? im[yi1*IMG_W + xi0] : 0.f;
        float v11 = (vx1&&vy1) ? im[yi1*IMG_W + xi1] : 0.f;
        g_crops[((long long)(ch*NIMG + ii)*CROPS + y)*CROPS + x] =
            v00*w00 + v01*w01 + v10*w10 + v11*w11;
    }
}

// ---------------- im2col kernels ----------------
__global__ void im2col1_kernel()
{
    long long e = (long long)blockIdx.x*blockDim.x + threadIdx.x;
    long long total = (long long)K1*N1;
    if (e >= total) return;
    int n1 = (int)(e % N1); int k = (int)(e / N1);
    int kx = k % 7, ky = (k/7) % 7, ch = k/49;
    int pos = n1 % (O1*O1); int img = n1 / (O1*O1);
    int ox = pos % O1, oy = pos / O1;
    int iy = oy*4 - 1 + ky, ix = ox*4 - 1 + kx;
    float v = 0.f;
    if (iy >= 0 && iy < CROPS && ix >= 0 && ix < CROPS)
        v = g_crops[((long long)(ch*NIMG + img)*CROPS + iy)*CROPS + ix];
    g_X1[e] = v;
}
__global__ void im2col2_kernel()
{
    long long e = (long long)blockIdx.x*blockDim.x + threadIdx.x;
    long long total = (long long)K2*N2;
    if (e >= total) return;
    int n2 = (int)(e % N2); int k = (int)(e / N2);
    int kx = k % 3, ky = (k/3) % 3, ic = k/9;
    int pos = n2 % (O2*O2); int img = n2 / (O2*O2);
    int ox = pos % O2, oy = pos / O2;
    int iy = oy*4 + ky, ix = ox*4 + kx;   // no padding, always in range
    g_X2[e] = g_h1[(long long)ic*N1 + (long long)img*(O1*O1) + iy*O1 + ix];
}
__global__ void im2col3_kernel()
{
    long long e = (long long)blockIdx.x*blockDim.x + threadIdx.x;
    long long total = (long long)K3*N3;
    if (e >= total) return;
    int n3 = (int)(e % N3); int k = (int)(e / N3);
    int kx = k % 3, ky = (k/3) % 3, ic = k/9;
    int pos = n3 % (O3*O3); int img = n3 / (O3*O3);
    int ox = pos % O3, oy = pos / O3;
    int iy = oy*2 + ky, ix = ox*2 + kx;   // pad hi=1
    float v = 0.f;
    if (iy < O2 && ix < O2)
        v = g_h2[(long long)ic*N2 + (long long)img*(O2*O2) + iy*O2 + ix];
    g_X3[e] = v;
}

// ---------------- TF32 tensor-core GEMM --------------------------------------
// C[M][N] = A[M][K] * B(K,N)  (B optionally transposed: B[N][K]),  optional relu.
// Tile 128x128x16, 256 threads = 8 warps (4 in M x 2 in N), warp tile 32x64.
// mma.sync.aligned.m16n8k8.row.col.f32.tf32.tf32.f32
#define GBM 128
#define GBN 128
#define GBK 16
#define SPAD 132   // smem row stride (padding kills quad bank conflicts)

__device__ __forceinline__ unsigned f2tf32(float f) {
    unsigned u;
    asm("cvt.rna.tf32.f32 %0, %1;" : "=r"(u) : "f"(f));
    return u;
}

__global__ __launch_bounds__(256) void tf32gemm_kernel(
    const float* __restrict__ A, const float* __restrict__ B, float* __restrict__ C,
    int M, int N, int K, int lda, int ldb, int ldc, int transb, int relu)
{
    __shared__ unsigned As[GBK*SPAD];   // [k][m]
    __shared__ unsigned Bs[GBK*SPAD];   // [k][n]

    int tid = threadIdx.x;
    int lane = tid & 31;
    int warp = tid >> 5;
    int wm = (warp & 3) * 32;      // warp row base within tile
    int wn = (warp >> 2) * 64;     // warp col base within tile
    int bx = blockIdx.x, by = blockIdx.y;

    float acc[2][8][4];
    #pragma unroll
    for (int i=0;i<2;i++)
        #pragma unroll
        for (int j=0;j<8;j++)
            #pragma unroll
            for (int q=0;q<4;q++) acc[i][j][q] = 0.f;

    int g = lane >> 2;       // group id 0..7
    int tg = lane & 3;       // thread-in-group 0..3

    for (int k0 = 0; k0 < K; k0 += GBK) {
        // load A tile: 128 rows x 16 k (coalesced along k)
        #pragma unroll
        for (int i = 0; i < 8; i++) {
            int idx = tid + i*256;
            int k = idx & 15, m = idx >> 4;
            int gr = by*GBM + m, gc = k0 + k;
            float v = (gr < M && gc < K) ? A[(long long)gr*lda + gc] : 0.f;
            As[k*SPAD + m] = f2tf32(v);
        }
        // load B tile: 16 k x 128 n (coalesced along n when !transb)
        #pragma unroll
        for (int i = 0; i < 8; i++) {
            int idx = tid + i*256;
            int k = idx >> 7, n = idx & 127;
            int gk = k0 + k, gn = bx*GBN + n;
            float v = 0.f;
            if (gk < K && gn < N)
                v = transb ? B[(long long)gn*ldb + gk] : B[(long long)gk*ldb + gn];
            Bs[k*SPAD + n] = f2tf32(v);
        }
        __syncthreads();

        #pragma unroll
        for (int ks = 0; ks < 2; ks++) {
            int kb = ks*8;
            unsigned af[2][4];
            #pragma unroll
            for (int mt = 0; mt < 2; mt++) {
                int r = wm + mt*16 + g;
                int c = kb + tg;
                af[mt][0] = As[c*SPAD + r];
                af[mt][1] = As[c*SPAD + r + 8];
                af[mt][2] = As[(c+4)*SPAD + r];
                af[mt][3] = As[(c+4)*SPAD + r + 8];
            }
            unsigned bf[8][2];
            #pragma unroll
            for (int nt = 0; nt < 8; nt++) {
                int col = wn + nt*8 + g;
                int kk = kb + tg;
                bf[nt][0] = Bs[kk*SPAD + col];
                bf[nt][1] = Bs[(kk+4)*SPAD + col];
            }
            #pragma unroll
            for (int mt = 0; mt < 2; mt++)
                #pragma unroll
                for (int nt = 0; nt < 8; nt++) {
                    asm volatile(
                        "mma.sync.aligned.m16n8k8.row.col.f32.tf32.tf32.f32 "
                        "{%0,%1,%2,%3}, {%4,%5,%6,%7}, {%8,%9}, {%0,%1,%2,%3};\n"
                        : "+f"(acc[mt][nt][0]), "+f"(acc[mt][nt][1]),
                          "+f"(acc[mt][nt][2]), "+f"(acc[mt][nt][3])
                        : "r"(af[mt][0]), "r"(af[mt][1]), "r"(af[mt][2]), "r"(af[mt][3]),
                          "r"(bf[nt][0]), "r"(bf[nt][1]));
                }
        }
        __syncthreads();
    }

    // epilogue
    #pragma unroll
    for (int mt = 0; mt < 2; mt++) {
        int r0 = by*GBM + wm + mt*16 + g;
        #pragma unroll
        for (int nt = 0; nt < 8; nt++) {
            int c0 = bx*GBN + wn + nt*8 + tg*2;
            float v0 = acc[mt][nt][0], v1 = acc[mt][nt][1];
            float v2 = acc[mt][nt][2], v3 = acc[mt][nt][3];
            if (relu) { v0=fmaxf(v0,0.f); v1=fmaxf(v1,0.f); v2=fmaxf(v2,0.f); v3=fmaxf(v3,0.f); }
            if (r0 < M) {
                if (c0   < N) C[(long long)r0*ldc + c0  ] = v0;
                if (c0+1 < N) C[(long long)r0*ldc + c0+1] = v1;
            }
            if (r0+8 < M) {
                if (c0   < N) C[(long long)(r0+8)*ldc + c0  ] = v2;
                if (c0+1 < N) C[(long long)(r0+8)*ldc + c0+1] = v3;
            }
        }
    }
}

// ---------------- tokens ----------------
__global__ void tok_kernel(const float* __restrict__ pos_embed)
{
    int i = blockIdx.x;
    for (int d = threadIdx.x; d < DIMK; d += blockDim.x) {
        const float* hp = g_h3 + (long long)d*N3 + (long long)i*49;
        float s = 0.f;
        #pragma unroll 7
        for (int p = 0; p < 49; p++) {
            float v = hp[p];
            s += v;
            g_tok[((long long)i*50 + 1 + p)*DIMK + d] = v + pos_embed[(1+p)*DIMK + d];
        }
        g_tok[(long long)i*50*DIMK + d] = s*(1.f/49.f) + pos_embed[d];
    }
}

// ---------------- attention (per image): logits/softmax/context -------------
__global__ void attn_kernel()
{
    int i = blockIdx.x;
    __shared__ float sS[DIMK];
    __shared__ float slog[64];
    const float* t = g_tok + (long long)i*50*DIMK;
    for (int d = threadIdx.x; d < DIMK; d += blockDim.x) sS[d] = g_S[i*DIMK + d];
    __syncthreads();

    int w = threadIdx.x >> 5, lane = threadIdx.x & 31;
    for (int j = w; j < 50; j += 8) {
        const float* tj = t + (long long)j*DIMK;
        float s = 0.f;
        for (int d = lane; d < DIMK; d += 32) s += sS[d]*tj[d];
        #pragma unroll
        for (int o = 16; o > 0; o >>= 1) s += __shfl_down_sync(0xffffffff, s, o);
        if (lane == 0) slog[j] = s * 0.03125f;   // DIM^-0.5
    }
    __syncthreads();
    if (threadIdx.x == 0) {
        float mx = slog[0];
        for (int j = 1; j < 50; j++) mx = fmaxf(mx, slog[j]);
        float sum = 0.f;
        for (int j = 0; j < 50; j++) { float e = expf(slog[j]-mx); slog[j]=e; sum+=e; }
        float inv = 1.f/sum;
        for (int j = 0; j < 50; j++) slog[j] *= inv;
    }
    __syncthreads();
    for (int d = threadIdx.x; d < DIMK; d += blockDim.x) {
        float c = 0.f;
        #pragma unroll 10
        for (int j = 0; j < 50; j++) c += slog[j]*t[(long long)j*DIMK + d];
        g_CTX[i*DIMK + d] = c;
    }
}

// ---------------- final EMA fuse ----------------
__global__ void fuse_kernel(const float* __restrict__ bdd,
                            const float* __restrict__ momentum,
                            float* __restrict__ out)
{
    int n = blockIdx.x;
    float mom = *momentum;
    const int order[6] = {2,0,1,5,3,4};
    for (int d = threadIdx.x; d < DIMK; d += blockDim.x) {
        float e = bdd[d];
        #pragma unroll
        for (int k = 0; k < 6; k++) {
            int c = order[k];
            int ii = n*NCC + c;
            if (g_valid[ii]) e = mom*e + (1.f - mom)*g_EMB[(long long)ii*DIMK + d];
        }
        out[n*DIMK + d] = e;
    }
}

// ---------------- launch ----------------
static inline float* sym(const void* s) {
    void* p = nullptr;
    cudaGetSymbolAddress(&p, s);
    return (float*)p;
}

extern "C" void kernel_launch(void* const* d_in, const int* in_sizes, int n_in,
                              void* d_out, int out_size)
{
    const float* camera_imgs = (const float*)d_in[0];
    const float* pred_boxes  = (const float*)d_in[1];
    const float* img_aug     = (const float*)d_in[2];
    const float* lidar_aug   = (const float*)d_in[3];
    const float* lidar2img   = (const float*)d_in[4];
    const float* momentum    = (const float*)d_in[5];
    const float* bdd         = (const float*)d_in[6];
    const float* theta_w     = (const float*)d_in[7];
    const float* theta_b     = (const float*)d_in[8];
    const float* conv1       = (const float*)d_in[9];
    const float* conv2       = (const float*)d_in[10];
    const float* conv3       = (const float*)d_in[11];
    const float* pos_embed   = (const float*)d_in[12];
    const float* wq          = (const float*)d_in[13];
    const float* wk          = (const float*)d_in[14];
    const float* wv          = (const float*)d_in[15];
    const float* wo          = (const float*)d_in[16];
    float* out = (float*)d_out;

    float* pX1  = sym(g_X1);   float* ph1 = sym(g_h1);
    float* pX2  = sym(g_X2);   float* ph2 = sym(g_h2);
    float* pX3  = sym(g_X3);   float* ph3 = sym(g_h3);
    float* ptok = sym(g_tok);  float* pM  = sym(g_M);
    float* pWvo = sym(g_Wvo);  float* pS  = sym(g_S);
    float* pCTX = sym(g_CTX);  float* pEMB= sym(g_EMB);

    // precompute M = wq @ wk^T ; Wvo = wv @ wo
    {
        dim3 g(DIMK/GBN, DIMK/GBM);
        tf32gemm_kernel<<<g,256>>>(wq, wk, pM,  DIMK, DIMK, DIMK, DIMK, DIMK, DIMK, 1, 0);
        tf32gemm_kernel<<<g,256>>>(wv, wo, pWvo,DIMK, DIMK, DIMK, DIMK, DIMK, DIMK, 0, 0);
    }

    // projection / theta
    theta_kernel<<<2,192>>>(pred_boxes, lidar_aug, lidar2img, img_aug, theta_w, theta_b);

    // grid sample
    {
        long long total = (long long)NIMG*CROPS*CROPS;
        sample_kernel<<<(unsigned)((total+255)/256),256>>>(camera_imgs);
    }

    // conv1
    {
        long long total = (long long)K1*N1;
        im2col1_kernel<<<(unsigned)((total+255)/256),256>>>();
        dim3 g((unsigned)((N1+GBN-1)/GBN), 1);
        tf32gemm_kernel<<<g,256>>>(conv1, pX1, ph1, 64, (int)N1, K1, K1, (int)N1, (int)N1, 0, 1);
    }
    // conv2
    {
        long long total = (long long)K2*N2;
        im2col2_kernel<<<(unsigned)((total+255)/256),256>>>();
        dim3 g((unsigned)((N2+GBN-1)/GBN), 2);
        tf32gemm_kernel<<<g,256>>>(conv2, pX2, ph2, 256, (int)N2, K2, K2, (int)N2, (int)N2, 0, 1);
    }
    // conv3
    {
        long long total = (long long)K3*N3;
        im2col3_kernel<<<(unsigned)((total+255)/256),256>>>();
        dim3 g((unsigned)((N3+GBN-1)/GBN), 8);
        tf32gemm_kernel<<<g,256>>>(conv3, pX3, ph3, 1024, (int)N3, K3, K3, (int)N3, (int)N3, 0, 1);
    }

    // tokens (+ pos embed, cls mean)
    tok_kernel<<<NIMG,256>>>(pos_embed);

    // S = tok0 @ M   (A rows strided by 50*DIMK)
    {
        dim3 g(DIMK/GBN, (NIMG+GBM-1)/GBM);
        tf32gemm_kernel<<<g,256>>>(ptok, pM, pS, NIMG, DIMK, DIMK, 50*DIMK, DIMK, DIMK, 0, 0);
    }

    // softmax + context
    attn_kernel<<<NIMG,256>>>();

    // EMB = CTX @ Wvo
    {
        dim3 g(DIMK/GBN, (NIMG+GBM-1)/GBM);
        tf32gemm_kernel<<<g,256>>>(pCTX, pWvo, pEMB, NIMG, DIMK, DIMK, DIMK, DIMK, DIMK, 0, 0);
    }

    // EMA fuse -> out (64 x 1024)
    fuse_kernel<<<NBOX,256>>>(bdd, momentum, out);
}

// round 3
// speedup vs baseline: 4.0309x; 1.3990x over previous
#include <cuda_runtime.h>
#include <math.h>

// ---------------- problem constants ----------------
#define DIMK   1024
#define IMG_H  512
#define IMG_W  1408
#define CROPS  224
#define BB     2
#define NCC    6
#define NBB    32
#define NBOX   (BB*NBB)        // 64
#define NIMG   (NBOX*NCC)      // 384

// conv geometry
#define O1 56
#define O2 14
#define O3 7
#define N1 ((long long)NIMG*O1*O1)   // 1204224
#define N2 ((long long)NIMG*O2*O2)   // 75264
#define N3 ((long long)NIMG*O3*O3)   // 18816
#define K1 (3*7*7)     // 147
#define K2 (64*3*3)    // 576
#define K3 (256*3*3)   // 2304

// ---------------- scratch (device globals; no alloc) ----------------
__device__ float g_theta[NIMG*6];
__device__ int   g_valid[NIMG];
__device__ float g_crops[3LL*NIMG*CROPS*CROPS];     // [ch][img][y][x]
__device__ float g_h1[64LL*N1];                     // [oc][img*pos]
__device__ float g_h2[256LL*N2];
__device__ float g_h3[1024LL*N3];
__device__ float g_tok[(long long)NIMG*50*DIMK];
__device__ float g_M[DIMK*DIMK];
__device__ float g_Wvo[DIMK*DIMK];
__device__ float g_S[NIMG*DIMK];
__device__ float g_CTX[NIMG*DIMK];
__device__ float g_EMB[NIMG*DIMK];

// ---------------- theta / projection ----------------
__global__ void theta_kernel(const float* __restrict__ boxes,
                             const float* __restrict__ la,
                             const float* __restrict__ l2i,
                             const float* __restrict__ aug,
                             const float* __restrict__ thw,
                             const float* __restrict__ thb)
{
    int t = blockIdx.x*blockDim.x + threadIdx.x;
    if (t >= NIMG) return;
    int c = t % NCC; int n = t / NCC; int b = n / NBB; int nb = n % NBB;
    const float* bx = boxes + (b*NBB + nb)*9;

    float r[4];
    #pragma unroll
    for (int i = 0; i < 4; i++) {
        float s = thb[i];
        #pragma unroll
        for (int j = 0; j < 9; j++) s += bx[j]*thw[i*9+j];
        r[i] = tanhf(s);
    }

    const float* L = la + b*16;
    float cx = bx[0]-L[3], cy = bx[1]-L[7], cz = bx[2]-L[11];
    float a00=L[0],a01=L[1],a02=L[2],a10=L[4],a11=L[5],a12=L[6],a20=L[8],a21=L[9],a22=L[10];
    float det = a00*(a11*a22-a12*a21) - a01*(a10*a22-a12*a20) + a02*(a10*a21-a11*a20);
    float id = 1.f/det;
    float x = ((a11*a22-a12*a21)*cx + (a02*a21-a01*a22)*cy + (a01*a12-a02*a11)*cz)*id;
    float y = ((a12*a20-a10*a22)*cx + (a00*a22-a02*a20)*cy + (a02*a10-a00*a12)*cz)*id;
    float z = ((a10*a21-a11*a20)*cx + (a01*a20-a00*a21)*cy + (a00*a11-a01*a10)*cz)*id;

    const float* P = l2i + (b*NCC + c)*16;
    float px = P[0]*x + P[1]*y + P[2]*z  + P[3];
    float py = P[4]*x + P[5]*y + P[6]*z  + P[7];
    float pz = P[8]*x + P[9]*y + P[10]*z + P[11];
    float zz = fminf(fmaxf(pz, 1e-5f), 100000.f);
    float qx = px/zz, qy = py/zz;
    const float* A = aug + (b*NCC + c)*16;
    float ux = A[0]*qx + A[1]*qy + A[2]*zz + A[3];
    float uy = A[4]*qx + A[5]*qy + A[6]*zz + A[7];

    int on = (uy < (float)IMG_H) && (uy >= 0.f) && (ux < (float)IMG_W) && (ux >= 0.f);
    float ty = uy/(float)IMG_H*2.f - 1.f;
    float tx = ux/(float)IMG_W*2.f - 1.f;

    g_theta[t*6+0]=r[0]; g_theta[t*6+1]=r[1]; g_theta[t*6+2]=tx;
    g_theta[t*6+3]=r[2]; g_theta[t*6+4]=r[3]; g_theta[t*6+5]=ty;
    g_valid[t] = on;
}

// ---------------- grid sample -> crops ----------------
__global__ void sample_kernel(const float* __restrict__ imgs)
{
    long long idx = (long long)blockIdx.x*blockDim.x + threadIdx.x;
    long long total = (long long)NIMG*CROPS*CROPS;
    if (idx >= total) return;
    int x = (int)(idx % CROPS);
    int y = (int)((idx / CROPS) % CROPS);
    int ii = (int)(idx / (CROPS*CROPS));
    int c = ii % NCC; int n = ii / NCC; int b = n / NBB;

    float t0 = g_theta[ii*6+0], t1 = g_theta[ii*6+1], t2 = g_theta[ii*6+2];
    float t3 = g_theta[ii*6+3], t4 = g_theta[ii*6+4], t5 = g_theta[ii*6+5];

    float gx = (2.f*x + 1.f)/(float)CROPS - 1.f;
    float gy = (2.f*y + 1.f)/(float)CROPS - 1.f;
    float g0 = gx*t0 + gy*t1 + t2;
    float g1 = gx*t3 + gy*t4 + t5;
    float ixf = ((g0 + 1.f)*(float)IMG_W - 1.f)*0.5f;
    float iyf = ((g1 + 1.f)*(float)IMG_H - 1.f)*0.5f;
    float x0 = floorf(ixf), y0 = floorf(iyf);
    float wx = ixf - x0,    wy = iyf - y0;
    float x1 = x0 + 1.f,    y1 = y0 + 1.f;
    bool vx0 = (x0 >= 0.f) && (x0 <= (float)(IMG_W-1));
    bool vx1 = (x1 >= 0.f) && (x1 <= (float)(IMG_W-1));
    bool vy0 = (y0 >= 0.f) && (y0 <= (float)(IMG_H-1));
    bool vy1 = (y1 >= 0.f) && (y1 <= (float)(IMG_H-1));
    int xi0 = (int)fminf(fmaxf(x0,0.f),(float)(IMG_W-1));
    int xi1 = (int)fminf(fmaxf(x1,0.f),(float)(IMG_W-1));
    int yi0 = (int)fminf(fmaxf(y0,0.f),(float)(IMG_H-1));
    int yi1 = (int)fminf(fmaxf(y1,0.f),(float)(IMG_H-1));
    float w00=(1.f-wx)*(1.f-wy), w01=wx*(1.f-wy), w10=(1.f-wx)*wy, w11=wx*wy;

    const float* base = imgs + (long long)(b*NCC + c)*3LL*IMG_H*IMG_W;
    #pragma unroll
    for (int ch = 0; ch < 3; ch++) {
        const float* im = base + (long long)ch*IMG_H*IMG_W;
        float v00 = (vx0&&vy0) ? im[yi0*IMG_W + xi0] : 0.f;
        float v01 = (vx1&&vy0) ? im[yi0*IMG_W + xi1] : 0.f;
        float v10 = (vx0&&vy1) ? im[yi1*IMG_W + xi0] : 0.f;
        float v11 = (vx1&&vy1) ? im[yi1*IMG_W + xi1] : 0.f;
        g_crops[((long long)(ch*NIMG + ii)*CROPS + y)*CROPS + x] =
            v00*w00 + v01*w01 + v10*w10 + v11*w11;
    }
}

// ---------------- helpers ----------------
__device__ __forceinline__ unsigned f2tf32(float f) {
    unsigned u;
    asm("cvt.rna.tf32.f32 %0, %1;" : "=r"(u) : "f"(f));
    return u;
}
__device__ __forceinline__ void cpasync4(unsigned dst, const float* src, bool pred) {
    asm volatile("cp.async.ca.shared.global [%0], [%1], 4, %2;\n"
        :: "r"(dst), "l"(src), "r"(pred ? 4 : 0) : "memory");
}
__device__ __forceinline__ void cpasync16(unsigned dst, const float* src) {
    asm volatile("cp.async.cg.shared.global [%0], [%1], 16;\n"
        :: "r"(dst), "l"(src) : "memory");
}
#define CP_COMMIT() asm volatile("cp.async.commit_group;\n" ::: "memory")
#define CP_WAIT1()  asm volatile("cp.async.wait_group 1;\n" ::: "memory")

// =====================================================================
// Pipelined implicit-GEMM, tf32 tensor cores.
// C[M][N] = A[M][K] * B(K,N);  B materialized on the fly per LOADER.
// Block tile BM x 128 x 16, 3-stage cp.async pipeline, 256 threads.
// smem layouts are fragment-native: addr(m,k)=(m>>3)*128+k*8+(m&7)
// (lane addr = tg*8+g -> 32 distinct banks, conflict-free).
// LOADER: 0=dense B[k][n], 1=conv1 gather, 2=conv2 gather, 3=conv3 gather
// =====================================================================
template<int LOADER, int BM, bool RELU>
__global__ __launch_bounds__(256) void pgemm(
    const float* __restrict__ A, const float* __restrict__ B, float* __restrict__ C,
    int M, int N, int K, int lda, int ldb, int ldc)
{
    constexpr int ASTG = BM*16;
    __shared__ float As[3][ASTG];
    __shared__ float Bs[3][2048];

    const int tid = threadIdx.x;
    const int bx = blockIdx.x, by = blockIdx.y;

    // ---- per-thread B-gather context (n fixed per thread) ----
    const int nloc = tid & 127;
    const int ngl  = bx*128 + nloc;
    const int bdst0 = (nloc>>3)*128 + (nloc&7);   // + krow*8
    const int krow0 = tid >> 7;                   // 0 or 1; krow = krow0 + 2*i

    // conv contexts
    long long cv_base = 0;  int cv_yb = 0, cv_xb = 0;
    if (LOADER == 1) {
        int img = ngl/3136; int pos = ngl - img*3136;
        int oy = pos/56, ox = pos - oy*56;
        cv_yb = oy*4 - 1; cv_xb = ox*4 - 1;
        cv_base = (long long)img*(CROPS*CROPS);
    } else if (LOADER == 2) {
        int img = ngl/196; int pos = ngl - img*196;
        int oy = pos/14, ox = pos - oy*14;
        cv_base = (long long)img*3136 + (long long)(oy*4)*56 + ox*4;
    } else if (LOADER == 3) {
        int img = ngl/49; int pos = ngl - img*49;
        int oy = pos/7, ox = pos - oy*7;
        cv_yb = oy*2; cv_xb = ox*2;
        cv_base = (long long)img*196;
    }

    unsigned sA0 = (unsigned)__cvta_generic_to_shared(&As[0][0]);
    unsigned sB0 = (unsigned)__cvta_generic_to_shared(&Bs[0][0]);

    // ---- stage loader ----
    auto load_stage = [&](int st, int k0) {
        unsigned sa = sA0 + (unsigned)(st*ASTG*4);
        unsigned sb = sB0 + (unsigned)(st*2048*4);
        // A: BM*16 elements, 4B cp.async, coalesced along k
        #pragma unroll
        for (int i = 0; i < ASTG/256; i++) {
            int e = tid + i*256;
            int k = e & 15, m = e >> 4;
            int gc = k0 + k;
            const float* src = A + (long long)(by*BM + m)*lda + gc;
            unsigned dst = sa + (unsigned)(((m>>3)*128 + k*8 + (m&7))*4);
            cpasync4(dst, src, gc < K);
        }
        if (LOADER == 0) {
            // dense B: 16B chunks along n
            #pragma unroll
            for (int i = 0; i < 2; i++) {
                int cch = tid + i*256;
                int k = cch >> 5; int n4 = (cch & 31)*4;
                const float* src = B + (long long)(k0 + k)*ldb + bx*128 + n4;
                unsigned dst = sb + (unsigned)((((n4>>3)*128) + k*8 + (n4&7))*4);
                cpasync16(dst, src);
            }
        } else {
            #pragma unroll
            for (int i = 0; i < 8; i++) {
                int krow = krow0 + 2*i;
                int k = k0 + krow;
                unsigned dst = sb + (unsigned)((bdst0 + krow*8)*4);
                if (LOADER == 1) {
                    int ch = k/49; int rr = k - ch*49;
                    int ky = rr/7, kx = rr - ky*7;
                    int iy = cv_yb + ky, ix = cv_xb + kx;
                    bool p = (k < K) && (iy >= 0) && (iy < CROPS) && (ix >= 0) && (ix < CROPS);
                    const float* src = B + ((long long)ch*NIMG*(CROPS*CROPS) + cv_base + (long long)iy*CROPS + ix);
                    cpasync4(dst, src, p);
                } else if (LOADER == 2) {
                    int ic = k/9; int rr = k - ic*9;
                    int ky = rr/3, kx = rr - ky*3;
                    const float* src = B + ((long long)ic*N1 + cv_base + ky*56 + kx);
                    cpasync4(dst, src, true);
                } else {
                    int ic = k/9; int rr = k - ic*9;
                    int ky = rr/3, kx = rr - ky*3;
                    int iy = cv_yb + ky, ix = cv_xb + kx;
                    bool p = (iy < 14) && (ix < 14);
                    const float* src = B + ((long long)ic*N2 + cv_base + iy*14 + ix);
                    cpasync4(dst, src, p);
                }
            }
        }
    };

    // ---- warp/fragment config ----
    constexpr int WMC = BM/32;          // warps along M
    constexpr int WN  = 128/(8/WMC);    // warp tile N
    constexpr int NT  = WN/8;
    const int lane = tid & 31, warp = tid >> 5;
    const int wm = (warp % WMC)*32;
    const int wn = (warp / WMC)*WN;
    const int g  = lane >> 2, tg = lane & 3;

    float acc[2][NT][4];
    #pragma unroll
    for (int i=0;i<2;i++)
        #pragma unroll
        for (int j=0;j<NT;j++)
            #pragma unroll
            for (int q=0;q<4;q++) acc[i][j][q] = 0.f;

    const int T = (K + 15)/16;

    load_stage(0, 0);  CP_COMMIT();
    load_stage(1, 16); CP_COMMIT();

    for (int kt = 0; kt < T; kt++) {
        CP_WAIT1();
        __syncthreads();
        int kn = kt + 2;
        if (kn < T) load_stage(kn % 3, kn*16);
        CP_COMMIT();

        const float* as = As[kt % 3];
        const float* bs = Bs[kt % 3];
        #pragma unroll
        for (int ks = 0; ks < 16; ks += 8) {
            unsigned af[2][4];
            #pragma unroll
            for (int mt = 0; mt < 2; mt++) {
                int base = ((wm + mt*16)>>3)*128 + (ks+tg)*8 + g;
                af[mt][0] = f2tf32(as[base]);
                af[mt][1] = f2tf32(as[base+128]);
                af[mt][2] = f2tf32(as[base+32]);
                af[mt][3] = f2tf32(as[base+160]);
            }
            unsigned bf[NT][2];
            #pragma unroll
            for (int nt = 0; nt < NT; nt++) {
                int base = ((wn>>3) + nt)*128 + (ks+tg)*8 + g;
                bf[nt][0] = f2tf32(bs[base]);
                bf[nt][1] = f2tf32(bs[base+32]);
            }
            #pragma unroll
            for (int mt = 0; mt < 2; mt++)
                #pragma unroll
                for (int nt = 0; nt < NT; nt++) {
                    asm volatile(
                        "mma.sync.aligned.m16n8k8.row.col.f32.tf32.tf32.f32 "
                        "{%0,%1,%2,%3}, {%4,%5,%6,%7}, {%8,%9}, {%0,%1,%2,%3};\n"
                        : "+f"(acc[mt][nt][0]), "+f"(acc[mt][nt][1]),
                          "+f"(acc[mt][nt][2]), "+f"(acc[mt][nt][3])
                        : "r"(af[mt][0]), "r"(af[mt][1]), "r"(af[mt][2]), "r"(af[mt][3]),
                          "r"(bf[nt][0]), "r"(bf[nt][1]));
                }
        }
        __syncthreads();
    }

    // ---- epilogue (M, N are exact multiples of tile dims) ----
    #pragma unroll
    for (int mt = 0; mt < 2; mt++) {
        int r0 = by*BM + wm + mt*16 + g;
        #pragma unroll
        for (int nt = 0; nt < NT; nt++) {
            int c0 = bx*128 + wn + nt*8 + tg*2;
            float v0 = acc[mt][nt][0], v1 = acc[mt][nt][1];
            float v2 = acc[mt][nt][2], v3 = acc[mt][nt][3];
            if (RELU) { v0=fmaxf(v0,0.f); v1=fmaxf(v1,0.f); v2=fmaxf(v2,0.f); v3=fmaxf(v3,0.f); }
            *reinterpret_cast<float2*>(C + (long long)r0*ldc + c0)     = make_float2(v0, v1);
            *reinterpret_cast<float2*>(C + (long long)(r0+8)*ldc + c0) = make_float2(v2, v3);
        }
    }
}

// ---------------- legacy tf32 GEMM (precompute M / Wvo, handles transb) -----
#define GBM 128
#define GBN 128
#define GBK 16
#define SPAD 132

__global__ __launch_bounds__(256) void tf32gemm_kernel(
    const float* __restrict__ A, const float* __restrict__ B, float* __restrict__ C,
    int M, int N, int K, int lda, int ldb, int ldc, int transb, int relu)
{
    __shared__ unsigned As[GBK*SPAD];
    __shared__ unsigned Bs[GBK*SPAD];

    int tid = threadIdx.x;
    int lane = tid & 31;
    int warp = tid >> 5;
    int wm = (warp & 3) * 32;
    int wn = (warp >> 2) * 64;
    int bx = blockIdx.x, by = blockIdx.y;

    float acc[2][8][4];
    #pragma unroll
    for (int i=0;i<2;i++)
        #pragma unroll
        for (int j=0;j<8;j++)
            #pragma unroll
            for (int q=0;q<4;q++) acc[i][j][q] = 0.f;

    int g = lane >> 2;
    int tg = lane & 3;

    for (int k0 = 0; k0 < K; k0 += GBK) {
        #pragma unroll
        for (int i = 0; i < 8; i++) {
            int idx = tid + i*256;
            int k = idx & 15, m = idx >> 4;
            int gr = by*GBM + m, gc = k0 + k;
            float v = (gr < M && gc < K) ? A[(long long)gr*lda + gc] : 0.f;
            As[k*SPAD + m] = f2tf32(v);
        }
        #pragma unroll
        for (int i = 0; i < 8; i++) {
            int idx = tid + i*256;
            int k = idx >> 7, n = idx & 127;
            int gk = k0 + k, gn = bx*GBN + n;
            float v = 0.f;
            if (gk < K && gn < N)
                v = transb ? B[(long long)gn*ldb + gk] : B[(long long)gk*ldb + gn];
            Bs[k*SPAD + n] = f2tf32(v);
        }
        __syncthreads();

        #pragma unroll
        for (int ks = 0; ks < 2; ks++) {
            int kb = ks*8;
            unsigned af[2][4];
            #pragma unroll
            for (int mt = 0; mt < 2; mt++) {
                int r = wm + mt*16 + g;
                int c = kb + tg;
                af[mt][0] = As[c*SPAD + r];
                af[mt][1] = As[c*SPAD + r + 8];
                af[mt][2] = As[(c+4)*SPAD + r];
                af[mt][3] = As[(c+4)*SPAD + r + 8];
            }
            unsigned bf[8][2];
            #pragma unroll
            for (int nt = 0; nt < 8; nt++) {
                int col = wn + nt*8 + g;
                int kk = kb + tg;
                bf[nt][0] = Bs[kk*SPAD + col];
                bf[nt][1] = Bs[(kk+4)*SPAD + col];
            }
            #pragma unroll
            for (int mt = 0; mt < 2; mt++)
                #pragma unroll
                for (int nt = 0; nt < 8; nt++) {
                    asm volatile(
                        "mma.sync.aligned.m16n8k8.row.col.f32.tf32.tf32.f32 "
                        "{%0,%1,%2,%3}, {%4,%5,%6,%7}, {%8,%9}, {%0,%1,%2,%3};\n"
                        : "+f"(acc[mt][nt][0]), "+f"(acc[mt][nt][1]),
                          "+f"(acc[mt][nt][2]), "+f"(acc[mt][nt][3])
                        : "r"(af[mt][0]), "r"(af[mt][1]), "r"(af[mt][2]), "r"(af[mt][3]),
                          "r"(bf[nt][0]), "r"(bf[nt][1]));
                }
        }
        __syncthreads();
    }

    #pragma unroll
    for (int mt = 0; mt < 2; mt++) {
        int r0 = by*GBM + wm + mt*16 + g;
        #pragma unroll
        for (int nt = 0; nt < 8; nt++) {
            int c0 = bx*GBN + wn + nt*8 + tg*2;
            float v0 = acc[mt][nt][0], v1 = acc[mt][nt][1];
            float v2 = acc[mt][nt][2], v3 = acc[mt][nt][3];
            if (relu) { v0=fmaxf(v0,0.f); v1=fmaxf(v1,0.f); v2=fmaxf(v2,0.f); v3=fmaxf(v3,0.f); }
            if (r0 < M) {
                if (c0   < N) C[(long long)r0*ldc + c0  ] = v0;
                if (c0+1 < N) C[(long long)r0*ldc + c0+1] = v1;
            }
            if (r0+8 < M) {
                if (c0   < N) C[(long long)(r0+8)*ldc + c0  ] = v2;
                if (c0+1 < N) C[(long long)(r0+8)*ldc + c0+1] = v3;
            }
        }
    }
}

// ---------------- tokens ----------------
__global__ void tok_kernel(const float* __restrict__ pos_embed)
{
    int i = blockIdx.x;
    for (int d = threadIdx.x; d < DIMK; d += blockDim.x) {
        const float* hp = g_h3 + (long long)d*N3 + (long long)i*49;
        float s = 0.f;
        #pragma unroll 7
        for (int p = 0; p < 49; p++) {
            float v = hp[p];
            s += v;
            g_tok[((long long)i*50 + 1 + p)*DIMK + d] = v + pos_embed[(1+p)*DIMK + d];
        }
        g_tok[(long long)i*50*DIMK + d] = s*(1.f/49.f) + pos_embed[d];
    }
}

// ---------------- attention ----------------
__global__ void attn_kernel()
{
    int i = blockIdx.x;
    __shared__ float sS[DIMK];
    __shared__ float slog[64];
    const float* t = g_tok + (long long)i*50*DIMK;
    for (int d = threadIdx.x; d < DIMK; d += blockDim.x) sS[d] = g_S[i*DIMK + d];
    __syncthreads();

    int w = threadIdx.x >> 5, lane = threadIdx.x & 31;
    for (int j = w; j < 50; j += 8) {
        const float* tj = t + (long long)j*DIMK;
        float s = 0.f;
        for (int d = lane; d < DIMK; d += 32) s += sS[d]*tj[d];
        #pragma unroll
        for (int o = 16; o > 0; o >>= 1) s += __shfl_down_sync(0xffffffff, s, o);
        if (lane == 0) slog[j] = s * 0.03125f;
    }
    __syncthreads();
    if (threadIdx.x == 0) {
        float mx = slog[0];
        for (int j = 1; j < 50; j++) mx = fmaxf(mx, slog[j]);
        float sum = 0.f;
        for (int j = 0; j < 50; j++) { float e = expf(slog[j]-mx); slog[j]=e; sum+=e; }
        float inv = 1.f/sum;
        for (int j = 0; j < 50; j++) slog[j] *= inv;
    }
    __syncthreads();
    for (int d = threadIdx.x; d < DIMK; d += blockDim.x) {
        float c = 0.f;
        #pragma unroll 10
        for (int j = 0; j < 50; j++) c += slog[j]*t[(long long)j*DIMK + d];
        g_CTX[i*DIMK + d] = c;
    }
}

// ---------------- final EMA fuse ----------------
__global__ void fuse_kernel(const float* __restrict__ bdd,
                            const float* __restrict__ momentum,
                            float* __restrict__ out)
{
    int n = blockIdx.x;
    float mom = *momentum;
    const int order[6] = {2,0,1,5,3,4};
    for (int d = threadIdx.x; d < DIMK; d += blockDim.x) {
        float e = bdd[d];
        #pragma unroll
        for (int k = 0; k < 6; k++) {
            int c = order[k];
            int ii = n*NCC + c;
            if (g_valid[ii]) e = mom*e + (1.f - mom)*g_EMB[(long long)ii*DIMK + d];
        }
        out[n*DIMK + d] = e;
    }
}

// ---------------- launch ----------------
static inline float* sym(const void* s) {
    void* p = nullptr;
    cudaGetSymbolAddress(&p, s);
    return (float*)p;
}

extern "C" void kernel_launch(void* const* d_in, const int* in_sizes, int n_in,
                              void* d_out, int out_size)
{
    const float* camera_imgs = (const float*)d_in[0];
    const float* pred_boxes  = (const float*)d_in[1];
    const float* img_aug     = (const float*)d_in[2];
    const float* lidar_aug   = (const float*)d_in[3];
    const float* lidar2img   = (const float*)d_in[4];
    const float* momentum    = (const float*)d_in[5];
    const float* bdd         = (const float*)d_in[6];
    const float* theta_w     = (const float*)d_in[7];
    const float* theta_b     = (const float*)d_in[8];
    const float* conv1       = (const float*)d_in[9];
    const float* conv2       = (const float*)d_in[10];
    const float* conv3       = (const float*)d_in[11];
    const float* pos_embed   = (const float*)d_in[12];
    const float* wq          = (const float*)d_in[13];
    const float* wk          = (const float*)d_in[14];
    const float* wv          = (const float*)d_in[15];
    const float* wo          = (const float*)d_in[16];
    float* out = (float*)d_out;

    float* pcrops = sym(g_crops);
    float* ph1 = sym(g_h1);
    float* ph2 = sym(g_h2);
    float* ph3 = sym(g_h3);
    float* ptok = sym(g_tok);  float* pM  = sym(g_M);
    float* pWvo = sym(g_Wvo);  float* pS  = sym(g_S);
    float* pCTX = sym(g_CTX);  float* pEMB= sym(g_EMB);

    // precompute M = wq @ wk^T ; Wvo = wv @ wo
    {
        dim3 g(DIMK/GBN, DIMK/GBM);
        tf32gemm_kernel<<<g,256>>>(wq, wk, pM,  DIMK, DIMK, DIMK, DIMK, DIMK, DIMK, 1, 0);
        tf32gemm_kernel<<<g,256>>>(wv, wo, pWvo,DIMK, DIMK, DIMK, DIMK, DIMK, DIMK, 0, 0);
    }

    // projection / theta
    theta_kernel<<<2,192>>>(pred_boxes, lidar_aug, lidar2img, img_aug, theta_w, theta_b);

    // grid sample
    {
        long long total = (long long)NIMG*CROPS*CROPS;
        sample_kernel<<<(unsigned)((total+255)/256),256>>>(camera_imgs);
    }

    // conv1: implicit im2col from crops.  M=64, N=N1, K=147
    {
        dim3 g((unsigned)(N1/128), 1);
        pgemm<1, 64, true><<<g,256>>>(conv1, pcrops, ph1, 64, (int)N1, K1, K1, 0, (int)N1);
    }
    // conv2: implicit im2col from h1.    M=256, N=N2, K=576
    {
        dim3 g((unsigned)(N2/128), 2);
        pgemm<2, 128, true><<<g,256>>>(conv2, ph1, ph2, 256, (int)N2, K2, K2, 0, (int)N2);
    }
    // conv3: implicit im2col from h2.    M=1024, N=N3, K=2304
    {
        dim3 g((unsigned)(N3/128), 8);
        pgemm<3, 128, true><<<g,256>>>(conv3, ph2, ph3, 1024, (int)N3, K3, K3, 0, (int)N3);
    }

    // tokens (+ pos embed, cls mean)
    tok_kernel<<<NIMG,256>>>(pos_embed);

    // S = tok0 @ M   (A rows strided by 50*DIMK)
    {
        dim3 g(DIMK/128, NIMG/128);
        pgemm<0, 128, false><<<g,256>>>(ptok, pM, pS, NIMG, DIMK, DIMK, 50*DIMK, DIMK, DIMK);
    }

    // softmax + context
    attn_kernel<<<NIMG,256>>>();

    // EMB = CTX @ Wvo
    {
        dim3 g(DIMK/128, NIMG/128);
        pgemm<0, 128, false><<<g,256>>>(pCTX, pWvo, pEMB, NIMG, DIMK, DIMK, DIMK, DIMK, DIMK);
    }

    // EMA fuse -> out (64 x 1024)
    fuse_kernel<<<NBOX,256>>>(bdd, momentum, out);
}